// round 1
// baseline (speedup 1.0000x reference)
#include <cuda_runtime.h>
#include <math.h>

// ---------------- problem constants ----------------
#define B_PTS   65536
#define C_DIM   2
#define V_OUT   3
#define D_DIM   64
#define K_CODES 1024
#define S_STAGES 4
#define H_DIM   1024
#define L_LAYERS 5
#define F_FREQ  25
#define IN_DIM  102     // C*(2F+1)
#define IN_PAD  112     // padded to multiple of 16 for the GEMM

// ---------------- device scratch (static, allocation-free) ----------------
__device__ float g_h0[(size_t)B_PTS * H_DIM];      // 256 MB ping
__device__ float g_h1[(size_t)B_PTS * H_DIM];      // 256 MB pong
__device__ float g_pe[(size_t)B_PTS * IN_PAD];     // padded positional encoding
__device__ float g_w0pad[IN_PAD * H_DIM];          // zero-padded dec_W0
__device__ float g_bias[L_LAYERS * H_DIM];         // dec_b + beta, per layer

// ---------------- kernel 1: RVQ + betas + combined biases ----------------
// Forward-pass algebra: z_q_st == z  =>  z_q_sum = sum_s img[s];
// idx[s] = argmin_k ||img[s] - cb[s][k]||^2 ; loss = 0.25 * mean per stage.
__global__ void vq_bias_kernel(const float* __restrict__ latents,
                               const int*   __restrict__ latent_idx,
                               const float* __restrict__ codebooks,
                               const float* __restrict__ mod_W,
                               const float* __restrict__ mod_b,
                               const float* __restrict__ dec_b0,
                               const float* __restrict__ dec_bh,
                               float* __restrict__ out_tail,
                               int write_tail)
{
    __shared__ float s_img[S_STAGES][D_DIM];
    __shared__ float s_zsum[D_DIM];
    __shared__ float s_min[256];
    __shared__ int   s_mi[256];
    __shared__ int   s_idx[S_STAGES];

    int tid = threadIdx.x;
    int li  = latent_idx[0];
    const float* img = latents + (size_t)li * S_STAGES * D_DIM;
    if (tid < S_STAGES * D_DIM) s_img[tid / D_DIM][tid % D_DIM] = img[tid];
    __syncthreads();

    for (int s = 0; s < S_STAGES; s++) {
        const float* z = s_img[s];
        float zz = 0.f;
        #pragma unroll
        for (int d = 0; d < D_DIM; d++) zz = fmaf(z[d], z[d], zz);

        float bmin = INFINITY; int bidx = 0x7fffffff;
        for (int k = tid; k < K_CODES; k += 256) {
            const float* e = codebooks + ((size_t)s * K_CODES + k) * D_DIM;
            float dot = 0.f, ee = 0.f;
            #pragma unroll
            for (int d = 0; d < D_DIM; d++) {
                float ev = e[d];
                dot = fmaf(z[d], ev, dot);
                ee  = fmaf(ev, ev, ee);
            }
            float dist = zz - 2.f * dot + ee;
            if (dist < bmin || (dist == bmin && k < bidx)) { bmin = dist; bidx = k; }
        }
        s_min[tid] = bmin; s_mi[tid] = bidx;
        __syncthreads();
        for (int off = 128; off > 0; off >>= 1) {
            if (tid < off) {
                float om = s_min[tid + off]; int oi = s_mi[tid + off];
                if (om < s_min[tid] || (om == s_min[tid] && oi < s_mi[tid])) {
                    s_min[tid] = om; s_mi[tid] = oi;
                }
            }
            __syncthreads();
        }
        if (tid == 0) s_idx[s] = s_mi[0];
        __syncthreads();
    }

    // z_sum = sum_s img[s]
    if (tid < D_DIM) {
        float v = 0.f;
        #pragma unroll
        for (int s = 0; s < S_STAGES; s++) v += s_img[s][tid];
        s_zsum[tid] = v;
    }
    __syncthreads();

    // tail outputs: idxs (as float) + total vq loss
    if (tid == 0 && write_tail) {
        float loss = 0.f;
        for (int s = 0; s < S_STAGES; s++) {
            const float* e = codebooks + ((size_t)s * K_CODES + s_idx[s]) * D_DIM;
            float acc = 0.f;
            for (int d = 0; d < D_DIM; d++) {
                float df = e[d] - s_img[s][d];
                acc = fmaf(df, df, acc);
            }
            loss += 0.25f * (acc / (float)D_DIM);
        }
        for (int s = 0; s < S_STAGES; s++) out_tail[s] = (float)s_idx[s];
        out_tail[S_STAGES] = loss;
    }

    // bias[l][h] = mod_b[l][h] + sum_d zsum[d]*mod_W[l][d][h] + (dec_b0 | dec_bh[l-1])
    for (int j = tid; j < L_LAYERS * H_DIM; j += 256) {
        int l = j / H_DIM, h = j % H_DIM;
        float acc = mod_b[j];
        #pragma unroll 8
        for (int d = 0; d < D_DIM; d++)
            acc = fmaf(s_zsum[d], mod_W[((size_t)l * D_DIM + d) * H_DIM + h], acc);
        acc += (l == 0) ? dec_b0[h] : dec_bh[(size_t)(l - 1) * H_DIM + h];
        g_bias[j] = acc;
    }
}

// ---------------- kernel 2: positional encoding (padded) ----------------
// pe[b, 0..1] = coords; pe[b, 2 + f*4 + t*2 + c] = {sin,cos}(coords[b,c] * 2^f * pi)
__global__ void pe_kernel(const float* __restrict__ coords)
{
    int idx = blockIdx.x * blockDim.x + threadIdx.x;
    if (idx >= B_PTS * IN_PAD) return;
    int b = idx / IN_PAD, j = idx % IN_PAD;
    float v;
    if (j < C_DIM) {
        v = coords[b * C_DIM + j];
    } else if (j < IN_DIM) {
        int r = j - C_DIM;
        int f = r >> 2;
        int t = (r >> 1) & 1;
        int c = r & 1;
        float fp  = ldexpf(3.14159265358979323846f, f);   // exact 2^f scaling of fp32 pi
        float ang = coords[b * C_DIM + c] * fp;
        v = t ? cosf(ang) : sinf(ang);
    } else {
        v = 0.f;   // zero padding
    }
    g_pe[(size_t)b * IN_PAD + j] = v;
}

// ---------------- kernel 3: pad dec_W0 to IN_PAD rows ----------------
__global__ void w0pad_kernel(const float* __restrict__ W0)
{
    int idx = blockIdx.x * blockDim.x + threadIdx.x;
    if (idx >= IN_PAD * H_DIM) return;
    int r = idx / H_DIM, c = idx % H_DIM;
    g_w0pad[idx] = (r < IN_DIM) ? W0[r * H_DIM + c] : 0.f;
}

// ---------------- kernel 4: fused GEMM + bias + relu ----------------
// C[M,N] = act(A[M,K] @ W[K,N] + bias[N]),  M=65536, N=1024, K in {112,1024}
// 128x128x16 tile, 256 threads, 8x8 microtile (split 4+4 for conflict-free LDS.128)
__global__ void __launch_bounds__(256, 2)
gemm_bias_act(const float* __restrict__ A, const float* __restrict__ W,
              const float* __restrict__ bias, float* __restrict__ C,
              int K, int relu)
{
    const int N = H_DIM;
    __shared__ float As[16][128];
    __shared__ float Bs[16][128];
    int tid = threadIdx.x;
    int bm = blockIdx.y * 128;
    int bn = blockIdx.x * 128;

    int arow = tid >> 2;          // 0..63   (+64 for second load)
    int acol = (tid & 3) << 2;    // 0,4,8,12
    int brow = tid >> 5;          // 0..7    (+8 for second load)
    int bcol = (tid & 31) << 2;   // 0..124
    int tm   = (tid >> 4) << 2;   // 0..60
    int tn   = (tid & 15) << 2;   // 0..60

    float acc[8][8];
    #pragma unroll
    for (int i = 0; i < 8; i++)
        #pragma unroll
        for (int j = 0; j < 8; j++) acc[i][j] = 0.f;

    for (int k0 = 0; k0 < K; k0 += 16) {
        #pragma unroll
        for (int i = 0; i < 2; i++) {
            int r = arow + i * 64;
            float4 v = *(const float4*)(A + (size_t)(bm + r) * K + k0 + acol);
            As[acol + 0][r] = v.x; As[acol + 1][r] = v.y;
            As[acol + 2][r] = v.z; As[acol + 3][r] = v.w;
        }
        #pragma unroll
        for (int i = 0; i < 2; i++) {
            int r = brow + i * 8;
            *(float4*)(&Bs[r][bcol]) = *(const float4*)(W + (size_t)(k0 + r) * N + bn + bcol);
        }
        __syncthreads();

        #pragma unroll
        for (int kk = 0; kk < 16; kk++) {
            float4 a0 = *(const float4*)(&As[kk][tm]);
            float4 a1 = *(const float4*)(&As[kk][tm + 64]);
            float4 b0 = *(const float4*)(&Bs[kk][tn]);
            float4 b1 = *(const float4*)(&Bs[kk][tn + 64]);
            float ra[8] = {a0.x, a0.y, a0.z, a0.w, a1.x, a1.y, a1.z, a1.w};
            float rb[8] = {b0.x, b0.y, b0.z, b0.w, b1.x, b1.y, b1.z, b1.w};
            #pragma unroll
            for (int i = 0; i < 8; i++)
                #pragma unroll
                for (int j = 0; j < 8; j++)
                    acc[i][j] = fmaf(ra[i], rb[j], acc[i][j]);
        }
        __syncthreads();
    }

    #pragma unroll
    for (int i = 0; i < 8; i++) {
        int r = bm + tm + ((i < 4) ? i : (60 + i));   // tm+i  or  tm+64+(i-4)
        #pragma unroll
        for (int jc = 0; jc < 2; jc++) {
            int cb = bn + tn + jc * 64;
            float4 v;
            v.x = acc[i][jc * 4 + 0] + bias[cb + 0];
            v.y = acc[i][jc * 4 + 1] + bias[cb + 1];
            v.z = acc[i][jc * 4 + 2] + bias[cb + 2];
            v.w = acc[i][jc * 4 + 3] + bias[cb + 3];
            if (relu) {
                v.x = fmaxf(v.x, 0.f); v.y = fmaxf(v.y, 0.f);
                v.z = fmaxf(v.z, 0.f); v.w = fmaxf(v.w, 0.f);
            }
            *(float4*)(C + (size_t)r * N + cb) = v;
        }
    }
}

// ---------------- kernel 5: output projection (H -> V=3) ----------------
__global__ void out_kernel(const float* __restrict__ h,
                           const float* __restrict__ Wout,
                           const float* __restrict__ bout,
                           float* __restrict__ out)
{
    int b = blockIdx.x;
    int tid = threadIdx.x;
    const float* hr = h + (size_t)b * H_DIM;
    float a0 = 0.f, a1 = 0.f, a2 = 0.f;
    for (int k = tid; k < H_DIM; k += 128) {
        float hv = hr[k];
        a0 = fmaf(hv, Wout[k * 3 + 0], a0);
        a1 = fmaf(hv, Wout[k * 3 + 1], a1);
        a2 = fmaf(hv, Wout[k * 3 + 2], a2);
    }
    #pragma unroll
    for (int off = 16; off; off >>= 1) {
        a0 += __shfl_down_sync(0xffffffffu, a0, off);
        a1 += __shfl_down_sync(0xffffffffu, a1, off);
        a2 += __shfl_down_sync(0xffffffffu, a2, off);
    }
    __shared__ float sr[4][3];
    int w = tid >> 5;
    if ((tid & 31) == 0) { sr[w][0] = a0; sr[w][1] = a1; sr[w][2] = a2; }
    __syncthreads();
    if (tid < V_OUT) {
        float v = bout[tid];
        #pragma unroll
        for (int ww = 0; ww < 4; ww++) v += sr[ww][tid];
        out[(size_t)b * V_OUT + tid] = v;
    }
}

// ---------------- launch ----------------
extern "C" void kernel_launch(void* const* d_in, const int* in_sizes, int n_in,
                              void* d_out, int out_size)
{
    const float* coords    = (const float*)d_in[0];
    const int*   latent_ix = (const int*)  d_in[1];
    const float* latents   = (const float*)d_in[2];
    const float* codebooks = (const float*)d_in[3];
    const float* mod_W     = (const float*)d_in[4];
    const float* mod_b     = (const float*)d_in[5];
    const float* dec_W0    = (const float*)d_in[6];
    const float* dec_b0    = (const float*)d_in[7];
    const float* dec_Wh    = (const float*)d_in[8];
    const float* dec_bh    = (const float*)d_in[9];
    const float* dec_Wout  = (const float*)d_in[10];
    const float* dec_bout  = (const float*)d_in[11];
    float* out = (float*)d_out;

    const int values_n = B_PTS * V_OUT;               // 196608
    int write_tail = (out_size >= values_n + S_STAGES + 1) ? 1 : 0;

    float *h0, *h1, *pe, *w0p, *bias;
    cudaGetSymbolAddress((void**)&h0,   g_h0);
    cudaGetSymbolAddress((void**)&h1,   g_h1);
    cudaGetSymbolAddress((void**)&pe,   g_pe);
    cudaGetSymbolAddress((void**)&w0p,  g_w0pad);
    cudaGetSymbolAddress((void**)&bias, g_bias);

    // stage A: tiny prep kernels (independent of the big GEMMs' inputs)
    vq_bias_kernel<<<1, 256>>>(latents, latent_ix, codebooks, mod_W, mod_b,
                               dec_b0, dec_bh, out + values_n, write_tail);
    pe_kernel<<<(B_PTS * IN_PAD + 255) / 256, 256>>>(coords);
    w0pad_kernel<<<(IN_PAD * H_DIM + 255) / 256, 256>>>(dec_W0);

    dim3 grid(H_DIM / 128, B_PTS / 128);   // (8, 512)

    // layer 0: pe(112) @ W0pad -> h0
    gemm_bias_act<<<grid, 256>>>(pe, w0p, bias + 0 * H_DIM, h0, IN_PAD, 1);
    // hidden layers 1..4 (ping-pong)
    gemm_bias_act<<<grid, 256>>>(h0, dec_Wh + 0 * (size_t)H_DIM * H_DIM, bias + 1 * H_DIM, h1, H_DIM, 1);
    gemm_bias_act<<<grid, 256>>>(h1, dec_Wh + 1 * (size_t)H_DIM * H_DIM, bias + 2 * H_DIM, h0, H_DIM, 1);
    gemm_bias_act<<<grid, 256>>>(h0, dec_Wh + 2 * (size_t)H_DIM * H_DIM, bias + 3 * H_DIM, h1, H_DIM, 1);
    gemm_bias_act<<<grid, 256>>>(h1, dec_Wh + 3 * (size_t)H_DIM * H_DIM, bias + 4 * H_DIM, h0, H_DIM, 1);
    // output projection
    out_kernel<<<B_PTS, 128>>>(h0, dec_Wout, dec_bout, out);
}

// round 6
// speedup vs baseline: 2.1389x; 2.1389x over previous
#include <cuda_runtime.h>
#include <cuda_bf16.h>
#include <stdint.h>
#include <math.h>

// ---------------- problem constants ----------------
#define B_PTS    65536
#define C_DIM    2
#define V_OUT    3
#define D_DIM    64
#define K_CODES  1024
#define S_STAGES 4
#define H_DIM    1024
#define L_LAYERS 5
#define F_FREQ   25
#define IN_DIM   102       // C*(2F+1)
#define K0_PAD   128       // layer-0 K padded to 2 chunks of 64

// ---------------- GEMM tiling ----------------
#define BM 128
#define BN 128
#define BK 64
#define NSTAGE 3
#define PLANE_BYTES  16384                  // 128 rows x 128B (64 bf16)
#define STAGE_BYTES  (4*PLANE_BYTES)        // Ah, Al, Bh, Bl = 64KB
#define SMEM_TOTAL   (NSTAGE*STAGE_BYTES)   // 192KB

// ---------------- device scratch (static, allocation-free) ----------------
__device__ __align__(256) uint32_t g_actA_hi[(size_t)B_PTS * H_DIM / 2];
__device__ __align__(256) uint32_t g_actA_lo[(size_t)B_PTS * H_DIM / 2];
__device__ __align__(256) uint32_t g_actB_hi[(size_t)B_PTS * H_DIM / 2];
__device__ __align__(256) uint32_t g_actB_lo[(size_t)B_PTS * H_DIM / 2];
__device__ __align__(256) uint32_t g_pe_hi[(size_t)B_PTS * K0_PAD / 2];
__device__ __align__(256) uint32_t g_pe_lo[(size_t)B_PTS * K0_PAD / 2];
__device__ __align__(256) uint32_t g_w0t_hi[H_DIM * K0_PAD / 2];
__device__ __align__(256) uint32_t g_w0t_lo[H_DIM * K0_PAD / 2];
__device__ __align__(256) uint32_t g_wht_hi[4ull * H_DIM * H_DIM / 2];
__device__ __align__(256) uint32_t g_wht_lo[4ull * H_DIM * H_DIM / 2];
__device__ float g_bias[L_LAYERS * H_DIM];
__device__ float g_zsum[D_DIM];

// ---------------- PTX helpers (all baseline sm_80+, valid on base sm_103) ----------------
__device__ __forceinline__ uint32_t smem_u32(const void* p) {
    uint32_t a;
    asm("{ .reg .u64 t; cvta.to.shared.u64 t, %1; cvt.u32.u64 %0, t; }" : "=r"(a) : "l"(p));
    return a;
}
__device__ __forceinline__ void cp_async16(uint32_t dst, const void* src) {
    asm volatile("cp.async.cg.shared.global [%0], [%1], 16;" :: "r"(dst), "l"(src) : "memory");
}
__device__ __forceinline__ void ldm_x4(uint32_t* r, uint32_t addr) {
    asm volatile("ldmatrix.sync.aligned.m8n8.x4.shared.b16 {%0,%1,%2,%3}, [%4];"
        : "=r"(r[0]), "=r"(r[1]), "=r"(r[2]), "=r"(r[3]) : "r"(addr));
}
__device__ __forceinline__ void mma_bf16(float* c, const uint32_t* a, uint32_t b0, uint32_t b1) {
    asm volatile("mma.sync.aligned.m16n8k16.row.col.f32.bf16.bf16.f32 "
        "{%0,%1,%2,%3}, {%4,%5,%6,%7}, {%8,%9}, {%0,%1,%2,%3};"
        : "+f"(c[0]), "+f"(c[1]), "+f"(c[2]), "+f"(c[3])
        : "r"(a[0]), "r"(a[1]), "r"(a[2]), "r"(a[3]), "r"(b0), "r"(b1));
}

// ---------------- staging: one K-chunk of A(hi,lo)+B(hi,lo) via cp.async ----------------
// smem planes are [128 rows][128B] with XOR swizzle: 16B chunk c stored at c ^ (row & 7).
__device__ __forceinline__ void stage_chunk(
    uint32_t stage_base,
    const __nv_bfloat16* Ahi, const __nv_bfloat16* Alo,
    const __nv_bfloat16* Bhi, const __nv_bfloat16* Blo,
    int bm, int bn, int kc, int K, int tid)
{
    #pragma unroll
    for (int it = 0; it < 4; it++) {
        int g = tid + it * 256;          // 0..1023
        int row = g >> 3, c = g & 7;
        uint32_t d = stage_base + (uint32_t)(row * 128 + ((c ^ (row & 7)) * 16));
        size_t aoff = (size_t)(bm + row) * K + kc + c * 8;
        size_t boff = (size_t)(bn + row) * K + kc + c * 8;
        cp_async16(d,                   Ahi + aoff);
        cp_async16(d + PLANE_BYTES,     Alo + aoff);
        cp_async16(d + 2 * PLANE_BYTES, Bhi + boff);
        cp_async16(d + 3 * PLANE_BYTES, Blo + boff);
    }
    asm volatile("cp.async.commit_group;" ::: "memory");
}

// ---------------- tensor-core MLP layer (mma.sync bf16, hi/lo 3-term split) ----------------
// C[M,N] = relu(A @ B^T + bias); A = Ahi+Alo [M,K] row-major; B = Bhi+Blo [N,K] K-major.
__global__ void __launch_bounds__(256, 1)
mlp_layer_kernel(const uint32_t* __restrict__ Ahi32, const uint32_t* __restrict__ Alo32,
                 const uint32_t* __restrict__ Bhi32, const uint32_t* __restrict__ Blo32,
                 const float* __restrict__ bias,
                 uint32_t* __restrict__ Chi32, uint32_t* __restrict__ Clo32,
                 int K)
{
    extern __shared__ char smem[];
    uint32_t sb = smem_u32(smem);
    int tid  = threadIdx.x;
    int lane = tid & 31;
    int wid  = tid >> 5;
    int wm = (wid >> 2) * 64;     // warp M offset within CTA tile
    int wn = (wid & 3) * 32;      // warp N offset
    int bm = blockIdx.y * BM;
    int bn = blockIdx.x * BN;
    int nch = K / BK;

    const __nv_bfloat16* Ahi = (const __nv_bfloat16*)Ahi32;
    const __nv_bfloat16* Alo = (const __nv_bfloat16*)Alo32;
    const __nv_bfloat16* Bhi = (const __nv_bfloat16*)Bhi32;
    const __nv_bfloat16* Blo = (const __nv_bfloat16*)Blo32;

    float acc[4][4][4];
    #pragma unroll
    for (int mi = 0; mi < 4; mi++)
        #pragma unroll
        for (int ni = 0; ni < 4; ni++)
            #pragma unroll
            for (int r = 0; r < 4; r++) acc[mi][ni][r] = 0.f;

    // prologue: fill pipeline
    int npro = (nch < NSTAGE) ? nch : NSTAGE;
    for (int p = 0; p < npro; p++)
        stage_chunk(sb + p * STAGE_BYTES, Ahi, Alo, Bhi, Blo, bm, bn, p * BK, K, tid);

    // precompute per-lane ldmatrix row components
    int arow_l = lane & 15;       // row within 16-row tile
    int seg    = lane >> 4;       // k-segment half (0/1)

    for (int i = 0; i < nch; i++) {
        int s = i % NSTAGE;
        int rem = nch - 1 - i;
        if (rem >= 2)      asm volatile("cp.async.wait_group 2;" ::: "memory");
        else if (rem == 1) asm volatile("cp.async.wait_group 1;" ::: "memory");
        else               asm volatile("cp.async.wait_group 0;" ::: "memory");
        __syncthreads();

        uint32_t aBase = sb + s * STAGE_BYTES;
        uint32_t bBase = aBase + 2 * PLANE_BYTES;

        #pragma unroll
        for (int k16 = 0; k16 < 4; k16++) {
            uint32_t ah[4][4], al[4][4];
            uint32_t bh[4][2], bl[4][2];
            // A fragments: 4 m16 tiles, hi+lo planes
            #pragma unroll
            for (int mi = 0; mi < 4; mi++) {
                int row = wm + mi * 16 + arow_l;
                uint32_t c = (uint32_t)((k16 * 2 + seg) ^ (row & 7));
                uint32_t addr = aBase + (uint32_t)(row * 128) + c * 16;
                ldm_x4(ah[mi], addr);
                ldm_x4(al[mi], addr + PLANE_BYTES);
            }
            // B fragments: 2 n16 groups -> 4 n8 frags, hi+lo
            #pragma unroll
            for (int ng = 0; ng < 2; ng++) {
                int row = wn + ng * 16 + arow_l;
                uint32_t c = (uint32_t)((k16 * 2 + seg) ^ (row & 7));
                uint32_t addr = bBase + (uint32_t)(row * 128) + c * 16;
                uint32_t t[4];
                ldm_x4(t, addr);
                bh[2 * ng][0] = t[0]; bh[2 * ng][1] = t[2];
                bh[2 * ng + 1][0] = t[1]; bh[2 * ng + 1][1] = t[3];
                ldm_x4(t, addr + PLANE_BYTES);
                bl[2 * ng][0] = t[0]; bl[2 * ng][1] = t[2];
                bl[2 * ng + 1][0] = t[1]; bl[2 * ng + 1][1] = t[3];
            }
            // 3-term MMAs
            #pragma unroll
            for (int mi = 0; mi < 4; mi++)
                #pragma unroll
                for (int ni = 0; ni < 4; ni++) {
                    mma_bf16(acc[mi][ni], ah[mi], bh[ni][0], bh[ni][1]);
                    mma_bf16(acc[mi][ni], ah[mi], bl[ni][0], bl[ni][1]);
                    mma_bf16(acc[mi][ni], al[mi], bh[ni][0], bh[ni][1]);
                }
        }
        __syncthreads();   // all warps done reading buffer s before refill

        if (i + NSTAGE < nch)
            stage_chunk(sb + s * STAGE_BYTES, Ahi, Alo, Bhi, Blo,
                        bm, bn, (i + NSTAGE) * BK, K, tid);
    }

    // epilogue: bias + relu + bf16 hi/lo split, packed u32 stores
    int qr = lane >> 2;            // 0..7
    int qc = (lane & 3) * 2;       // 0,2,4,6
    #pragma unroll
    for (int mi = 0; mi < 4; mi++) {
        #pragma unroll
        for (int ni = 0; ni < 4; ni++) {
            int col = bn + wn + ni * 8 + qc;
            float b0 = bias[col], b1 = bias[col + 1];
            #pragma unroll
            for (int half = 0; half < 2; half++) {
                int row = bm + wm + mi * 16 + qr + half * 8;
                float v0 = acc[mi][ni][half * 2 + 0] + b0;
                float v1 = acc[mi][ni][half * 2 + 1] + b1;
                v0 = fmaxf(v0, 0.f); v1 = fmaxf(v1, 0.f);
                __nv_bfloat16 h0 = __float2bfloat16(v0);
                __nv_bfloat16 h1 = __float2bfloat16(v1);
                __nv_bfloat16 l0 = __float2bfloat16(v0 - __bfloat162float(h0));
                __nv_bfloat16 l1 = __float2bfloat16(v1 - __bfloat162float(h1));
                size_t go = (size_t)row * (H_DIM / 2) + (col >> 1);
                Chi32[go] = ((uint32_t)__bfloat16_as_ushort(h1) << 16) | __bfloat16_as_ushort(h0);
                Clo32[go] = ((uint32_t)__bfloat16_as_ushort(l1) << 16) | __bfloat16_as_ushort(l0);
            }
        }
    }
}

// ---------------- RVQ: indices, loss, z_sum ----------------
__global__ void vq_kernel(const float* __restrict__ latents,
                          const int*   __restrict__ latent_idx,
                          const float* __restrict__ codebooks,
                          float* __restrict__ out_tail, int write_tail)
{
    __shared__ float s_img[S_STAGES][D_DIM];
    __shared__ float s_min[256];
    __shared__ int   s_mi[256];
    __shared__ int   s_idx[S_STAGES];

    int tid = threadIdx.x;
    int li = latent_idx[0];
    const float* img = latents + (size_t)li * S_STAGES * D_DIM;
    if (tid < S_STAGES * D_DIM) s_img[tid / D_DIM][tid % D_DIM] = img[tid];
    __syncthreads();

    for (int s = 0; s < S_STAGES; s++) {
        const float* z = s_img[s];
        float zz = 0.f;
        #pragma unroll
        for (int d = 0; d < D_DIM; d++) zz = fmaf(z[d], z[d], zz);
        float bmin = INFINITY; int bidx = 0x7fffffff;
        for (int k = tid; k < K_CODES; k += 256) {
            const float* e = codebooks + ((size_t)s * K_CODES + k) * D_DIM;
            float dot = 0.f, ee = 0.f;
            #pragma unroll
            for (int d = 0; d < D_DIM; d++) {
                float ev = e[d];
                dot = fmaf(z[d], ev, dot);
                ee  = fmaf(ev, ev, ee);
            }
            float dist = zz - 2.f * dot + ee;
            if (dist < bmin || (dist == bmin && k < bidx)) { bmin = dist; bidx = k; }
        }
        s_min[tid] = bmin; s_mi[tid] = bidx;
        __syncthreads();
        for (int off = 128; off > 0; off >>= 1) {
            if (tid < off) {
                float om = s_min[tid + off]; int oi = s_mi[tid + off];
                if (om < s_min[tid] || (om == s_min[tid] && oi < s_mi[tid])) {
                    s_min[tid] = om; s_mi[tid] = oi;
                }
            }
            __syncthreads();
        }
        if (tid == 0) s_idx[s] = s_mi[0];
        __syncthreads();
    }

    if (tid < D_DIM) {
        float v = 0.f;
        #pragma unroll
        for (int s = 0; s < S_STAGES; s++) v += s_img[s][tid];
        g_zsum[tid] = v;
    }
    if (tid == 0 && write_tail) {
        float loss = 0.f;
        for (int s = 0; s < S_STAGES; s++) {
            const float* e = codebooks + ((size_t)s * K_CODES + s_idx[s]) * D_DIM;
            float acc = 0.f;
            for (int d = 0; d < D_DIM; d++) {
                float df = e[d] - s_img[s][d];
                acc = fmaf(df, df, acc);
            }
            loss += 0.25f * (acc / (float)D_DIM);
        }
        for (int s = 0; s < S_STAGES; s++) out_tail[s] = (float)s_idx[s];
        out_tail[S_STAGES] = loss;
    }
}

// ---------------- combined bias: mod_b + zsum@mod_W + dec bias ----------------
__global__ void bias_kernel(const float* __restrict__ mod_W, const float* __restrict__ mod_b,
                            const float* __restrict__ dec_b0, const float* __restrict__ dec_bh)
{
    __shared__ float zs[D_DIM];
    int j = blockIdx.x * 256 + threadIdx.x;   // < 5120
    if (threadIdx.x < D_DIM) zs[threadIdx.x] = g_zsum[threadIdx.x];
    __syncthreads();
    int l = j >> 10, h = j & 1023;
    float acc = mod_b[j];
    #pragma unroll 8
    for (int d = 0; d < D_DIM; d++)
        acc = fmaf(zs[d], mod_W[((size_t)l * D_DIM + d) * H_DIM + h], acc);
    acc += (l == 0) ? dec_b0[h] : dec_bh[(size_t)(l - 1) * H_DIM + h];
    g_bias[j] = acc;
}

// ---------------- positional encoding -> bf16 hi/lo planes (K padded to 128) ----------------
__global__ void pe_kernel(const float* __restrict__ coords)
{
    int idx = blockIdx.x * blockDim.x + threadIdx.x;
    if (idx >= B_PTS * K0_PAD) return;
    int b = idx >> 7, j = idx & 127;
    float v = 0.f;
    if (j < C_DIM) {
        v = coords[b * C_DIM + j];
    } else if (j < IN_DIM) {
        int r = j - C_DIM;
        int f = r >> 2;
        int t = (r >> 1) & 1;
        int c = r & 1;
        float fp = ldexpf(3.14159265358979323846f, f);
        float ang = coords[b * C_DIM + c] * fp;
        v = t ? cosf(ang) : sinf(ang);
    }
    __nv_bfloat16 h = __float2bfloat16(v);
    ((__nv_bfloat16*)g_pe_hi)[idx] = h;
    ((__nv_bfloat16*)g_pe_lo)[idx] = __float2bfloat16(v - __bfloat162float(h));
}

// ---------------- weight transpose + bf16 hi/lo split ----------------
// src [z][Ksrc][N] fp32 -> dst [z][N][Kpad] bf16 (zero-padded K)
__global__ void wtrans_kernel(const float* __restrict__ src, int Ksrc, int Kpad, int Ncols,
                              uint32_t* __restrict__ dst_hi32, uint32_t* __restrict__ dst_lo32)
{
    int z = blockIdx.z;
    const float* s = src + (size_t)z * Ksrc * Ncols;
    __nv_bfloat16* dh = (__nv_bfloat16*)dst_hi32 + (size_t)z * Ncols * Kpad;
    __nv_bfloat16* dl = (__nv_bfloat16*)dst_lo32 + (size_t)z * Ncols * Kpad;
    __shared__ float tile[32][33];
    int k0 = blockIdx.x * 32, n0 = blockIdx.y * 32;
    for (int yy = threadIdx.y; yy < 32; yy += 8) {
        int k = k0 + yy;
        tile[yy][threadIdx.x] = (k < Ksrc) ? s[(size_t)k * Ncols + n0 + threadIdx.x] : 0.f;
    }
    __syncthreads();
    for (int yy = threadIdx.y; yy < 32; yy += 8) {
        int n = n0 + yy, k = k0 + threadIdx.x;
        float v = tile[threadIdx.x][yy];
        __nv_bfloat16 h = __float2bfloat16(v);
        dh[(size_t)n * Kpad + k] = h;
        dl[(size_t)n * Kpad + k] = __float2bfloat16(v - __bfloat162float(h));
    }
}

// ---------------- output projection (H -> 3) ----------------
__global__ void out_kernel(const uint32_t* __restrict__ hi32, const uint32_t* __restrict__ lo32,
                           const float* __restrict__ Wout, const float* __restrict__ bout,
                           float* __restrict__ out)
{
    int b = blockIdx.x;
    int tid = threadIdx.x;
    const uint32_t* h32 = hi32 + (size_t)b * (H_DIM / 2);
    const uint32_t* l32 = lo32 + (size_t)b * (H_DIM / 2);
    float a0 = 0.f, a1 = 0.f, a2 = 0.f;
    for (int k2 = tid; k2 < H_DIM / 2; k2 += 128) {
        uint32_t hv = h32[k2], lv = l32[k2];
        __nv_bfloat162 hp = *reinterpret_cast<const __nv_bfloat162*>(&hv);
        __nv_bfloat162 lp = *reinterpret_cast<const __nv_bfloat162*>(&lv);
        float2 hf = __bfloat1622float2(hp);
        float2 lf = __bfloat1622float2(lp);
        float v0 = hf.x + lf.x, v1 = hf.y + lf.y;
        int k = 2 * k2;
        a0 = fmaf(v0, Wout[k * 3 + 0], a0); a0 = fmaf(v1, Wout[(k + 1) * 3 + 0], a0);
        a1 = fmaf(v0, Wout[k * 3 + 1], a1); a1 = fmaf(v1, Wout[(k + 1) * 3 + 1], a1);
        a2 = fmaf(v0, Wout[k * 3 + 2], a2); a2 = fmaf(v1, Wout[(k + 1) * 3 + 2], a2);
    }
    #pragma unroll
    for (int off = 16; off; off >>= 1) {
        a0 += __shfl_down_sync(0xffffffffu, a0, off);
        a1 += __shfl_down_sync(0xffffffffu, a1, off);
        a2 += __shfl_down_sync(0xffffffffu, a2, off);
    }
    __shared__ float sr[4][3];
    int w = tid >> 5;
    if ((tid & 31) == 0) { sr[w][0] = a0; sr[w][1] = a1; sr[w][2] = a2; }
    __syncthreads();
    if (tid < V_OUT) {
        float v = bout[tid];
        #pragma unroll
        for (int ww = 0; ww < 4; ww++) v += sr[ww][tid];
        out[(size_t)b * V_OUT + tid] = v;
    }
}

// ---------------- launch ----------------
extern "C" void kernel_launch(void* const* d_in, const int* in_sizes, int n_in,
                              void* d_out, int out_size)
{
    const float* coords    = (const float*)d_in[0];
    const int*   latent_ix = (const int*)  d_in[1];
    const float* latents   = (const float*)d_in[2];
    const float* codebooks = (const float*)d_in[3];
    const float* mod_W     = (const float*)d_in[4];
    const float* mod_b     = (const float*)d_in[5];
    const float* dec_W0    = (const float*)d_in[6];
    const float* dec_b0    = (const float*)d_in[7];
    const float* dec_Wh    = (const float*)d_in[8];
    const float* dec_bh    = (const float*)d_in[9];
    const float* dec_Wout  = (const float*)d_in[10];
    const float* dec_bout  = (const float*)d_in[11];
    float* out = (float*)d_out;

    const int values_n = B_PTS * V_OUT;
    int write_tail = (out_size >= values_n + S_STAGES + 1) ? 1 : 0;

    cudaFuncSetAttribute(mlp_layer_kernel, cudaFuncAttributeMaxDynamicSharedMemorySize, SMEM_TOTAL);

    uint32_t *Ahi, *Alo, *Bhi, *Blo, *peh, *pel, *w0h, *w0l, *whh, *whl;
    float *bias;
    cudaGetSymbolAddress((void**)&Ahi, g_actA_hi);
    cudaGetSymbolAddress((void**)&Alo, g_actA_lo);
    cudaGetSymbolAddress((void**)&Bhi, g_actB_hi);
    cudaGetSymbolAddress((void**)&Blo, g_actB_lo);
    cudaGetSymbolAddress((void**)&peh, g_pe_hi);
    cudaGetSymbolAddress((void**)&pel, g_pe_lo);
    cudaGetSymbolAddress((void**)&w0h, g_w0t_hi);
    cudaGetSymbolAddress((void**)&w0l, g_w0t_lo);
    cudaGetSymbolAddress((void**)&whh, g_wht_hi);
    cudaGetSymbolAddress((void**)&whl, g_wht_lo);
    cudaGetSymbolAddress((void**)&bias, g_bias);

    // prep
    vq_kernel<<<1, 256>>>(latents, latent_ix, codebooks, out + values_n, write_tail);
    bias_kernel<<<20, 256>>>(mod_W, mod_b, dec_b0, dec_bh);
    pe_kernel<<<(B_PTS * K0_PAD + 255) / 256, 256>>>(coords);
    {
        dim3 blk(32, 8);
        wtrans_kernel<<<dim3(K0_PAD / 32, H_DIM / 32, 1), blk>>>(dec_W0, IN_DIM, K0_PAD, H_DIM, w0h, w0l);
        wtrans_kernel<<<dim3(H_DIM / 32, H_DIM / 32, 4), blk>>>(dec_Wh, H_DIM, H_DIM, H_DIM, whh, whl);
    }

    dim3 grid(H_DIM / BN, B_PTS / BM);   // (8, 512)
    size_t WH = (size_t)H_DIM * H_DIM / 2;

    // layer 0: pe(128) @ W0^T -> actA
    mlp_layer_kernel<<<grid, 256, SMEM_TOTAL>>>(peh, pel, w0h, w0l, bias + 0 * H_DIM, Ahi, Alo, K0_PAD);
    // hidden layers 1..4 (ping-pong actA <-> actB)
    mlp_layer_kernel<<<grid, 256, SMEM_TOTAL>>>(Ahi, Alo, whh + 0 * WH, whl + 0 * WH, bias + 1 * H_DIM, Bhi, Blo, H_DIM);
    mlp_layer_kernel<<<grid, 256, SMEM_TOTAL>>>(Bhi, Blo, whh + 1 * WH, whl + 1 * WH, bias + 2 * H_DIM, Ahi, Alo, H_DIM);
    mlp_layer_kernel<<<grid, 256, SMEM_TOTAL>>>(Ahi, Alo, whh + 2 * WH, whl + 2 * WH, bias + 3 * H_DIM, Bhi, Blo, H_DIM);
    mlp_layer_kernel<<<grid, 256, SMEM_TOTAL>>>(Bhi, Blo, whh + 3 * WH, whl + 3 * WH, bias + 4 * H_DIM, Ahi, Alo, H_DIM);
    // output projection
    out_kernel<<<B_PTS, 128>>>(Ahi, Alo, dec_Wout, dec_bout, out);
}

// round 11
// speedup vs baseline: 2.1612x; 1.0104x over previous
#include <cuda_runtime.h>
#include <cuda_bf16.h>
#include <stdint.h>
#include <math.h>

// ---------------- problem constants ----------------
#define B_PTS    65536
#define C_DIM    2
#define V_OUT    3
#define D_DIM    64
#define K_CODES  1024
#define S_STAGES 4
#define H_DIM    1024
#define L_LAYERS 5
#define F_FREQ   25
#define IN_DIM   102       // C*(2F+1)
#define K0_PAD   128       // layer-0 K padded to 2 chunks of 64

// ---------------- GEMM tiling ----------------
#define BM 256
#define BN 128
#define BK 64
#define NSTAGE 2
#define THREADS 512
#define A_PLANE  32768                      // 256 rows x 128B (64 bf16)
#define B_PLANE  16384                      // 128 rows x 128B
#define STAGE_BYTES  (2*A_PLANE + 2*B_PLANE)   // 96KB
#define SMEM_TOTAL   (NSTAGE*STAGE_BYTES)      // 192KB

// ---------------- device scratch (static, allocation-free) ----------------
__device__ __align__(256) uint32_t g_actA_hi[(size_t)B_PTS * H_DIM / 2];
__device__ __align__(256) uint32_t g_actA_lo[(size_t)B_PTS * H_DIM / 2];
__device__ __align__(256) uint32_t g_actB_hi[(size_t)B_PTS * H_DIM / 2];
__device__ __align__(256) uint32_t g_actB_lo[(size_t)B_PTS * H_DIM / 2];
__device__ __align__(256) uint32_t g_pe_hi[(size_t)B_PTS * K0_PAD / 2];
__device__ __align__(256) uint32_t g_pe_lo[(size_t)B_PTS * K0_PAD / 2];
__device__ __align__(256) uint32_t g_w0t_hi[H_DIM * K0_PAD / 2];
__device__ __align__(256) uint32_t g_w0t_lo[H_DIM * K0_PAD / 2];
__device__ __align__(256) uint32_t g_wht_hi[4ull * H_DIM * H_DIM / 2];
__device__ __align__(256) uint32_t g_wht_lo[4ull * H_DIM * H_DIM / 2];
__device__ float g_bias[L_LAYERS * H_DIM];
__device__ float g_zsum[D_DIM];

// ---------------- PTX helpers (baseline sm_80+, valid on base sm_103) ----------------
__device__ __forceinline__ uint32_t smem_u32(const void* p) {
    uint32_t a;
    asm("{ .reg .u64 t; cvta.to.shared.u64 t, %1; cvt.u32.u64 %0, t; }" : "=r"(a) : "l"(p));
    return a;
}
__device__ __forceinline__ void cp_async16(uint32_t dst, const void* src) {
    asm volatile("cp.async.cg.shared.global [%0], [%1], 16;" :: "r"(dst), "l"(src) : "memory");
}
__device__ __forceinline__ void ldm_x4(uint32_t* r, uint32_t addr) {
    asm volatile("ldmatrix.sync.aligned.m8n8.x4.shared.b16 {%0,%1,%2,%3}, [%4];"
        : "=r"(r[0]), "=r"(r[1]), "=r"(r[2]), "=r"(r[3]) : "r"(addr));
}
__device__ __forceinline__ void mma_bf16(float* c, const uint32_t* a, uint32_t b0, uint32_t b1) {
    asm volatile("mma.sync.aligned.m16n8k16.row.col.f32.bf16.bf16.f32 "
        "{%0,%1,%2,%3}, {%4,%5,%6,%7}, {%8,%9}, {%0,%1,%2,%3};"
        : "+f"(c[0]), "+f"(c[1]), "+f"(c[2]), "+f"(c[3])
        : "r"(a[0]), "r"(a[1]), "r"(a[2]), "r"(a[3]), "r"(b0), "r"(b1));
}

// ---------------- staging: one K-chunk of A(hi,lo)+B(hi,lo) via cp.async ----------------
// planes are [rows][128B] with XOR swizzle: 16B chunk c of row stored at c ^ (row & 7).
__device__ __forceinline__ void stage_chunk(
    uint32_t stage_base,
    const __nv_bfloat16* Ahi, const __nv_bfloat16* Alo,
    const __nv_bfloat16* Bhi, const __nv_bfloat16* Blo,
    int bm, int bn, int kc, int K, int tid)
{
    // A planes: 256 rows x 8 granules = 2048 granules of 16B
    #pragma unroll
    for (int it = 0; it < 4; it++) {
        int g = tid + it * THREADS;
        int row = g >> 3, c = g & 7;
        uint32_t d = stage_base + (uint32_t)(row * 128 + ((c ^ (row & 7)) * 16));
        size_t aoff = (size_t)(bm + row) * K + kc + c * 8;
        cp_async16(d,           Ahi + aoff);
        cp_async16(d + A_PLANE, Alo + aoff);
    }
    // B planes: 128 rows x 8 granules = 1024 granules
    #pragma unroll
    for (int it = 0; it < 2; it++) {
        int g = tid + it * THREADS;
        int row = g >> 3, c = g & 7;
        uint32_t d = stage_base + 2 * A_PLANE + (uint32_t)(row * 128 + ((c ^ (row & 7)) * 16));
        size_t boff = (size_t)(bn + row) * K + kc + c * 8;
        cp_async16(d,           Bhi + boff);
        cp_async16(d + B_PLANE, Blo + boff);
    }
    asm volatile("cp.async.commit_group;" ::: "memory");
}

// ---------------- tensor-core MLP layer (mma.sync bf16, hi/lo 3-term split) ----------------
// C[M,N] = relu(A @ B^T + bias); A = Ahi+Alo [M,K] row-major; B = Bhi+Blo [N,K] K-major.
__global__ void __launch_bounds__(THREADS, 1)
mlp_layer_kernel(const uint32_t* __restrict__ Ahi32, const uint32_t* __restrict__ Alo32,
                 const uint32_t* __restrict__ Bhi32, const uint32_t* __restrict__ Blo32,
                 const float* __restrict__ bias,
                 uint32_t* __restrict__ Chi32, uint32_t* __restrict__ Clo32,
                 int K)
{
    extern __shared__ char smem[];
    uint32_t sb = smem_u32(smem);
    int tid  = threadIdx.x;
    int lane = tid & 31;
    int wid  = tid >> 5;                   // 0..15
    int wm = (wid >> 2) * 64;              // warp M offset (0,64,128,192)
    int wn = (wid & 3) * 32;               // warp N offset (0,32,64,96)
    int bm = blockIdx.y * BM;
    int bn = blockIdx.x * BN;
    int nch = K / BK;

    const __nv_bfloat16* Ahi = (const __nv_bfloat16*)Ahi32;
    const __nv_bfloat16* Alo = (const __nv_bfloat16*)Alo32;
    const __nv_bfloat16* Bhi = (const __nv_bfloat16*)Bhi32;
    const __nv_bfloat16* Blo = (const __nv_bfloat16*)Blo32;

    float acc[4][4][4];
    #pragma unroll
    for (int mi = 0; mi < 4; mi++)
        #pragma unroll
        for (int ni = 0; ni < 4; ni++)
            #pragma unroll
            for (int r = 0; r < 4; r++) acc[mi][ni][r] = 0.f;

    // prologue: fill both stages
    stage_chunk(sb,               Ahi, Alo, Bhi, Blo, bm, bn, 0,  K, tid);
    if (nch > 1)
        stage_chunk(sb + STAGE_BYTES, Ahi, Alo, Bhi, Blo, bm, bn, BK, K, tid);

    int arow_l = lane & 15;       // row within 16-row tile
    int seg    = lane >> 4;       // k-segment half (0/1)

    for (int i = 0; i < nch; i++) {
        int s = i & 1;
        if (i == nch - 1) asm volatile("cp.async.wait_group 0;" ::: "memory");
        else              asm volatile("cp.async.wait_group 1;" ::: "memory");
        __syncthreads();

        uint32_t aBase = sb + s * STAGE_BYTES;
        uint32_t bBase = aBase + 2 * A_PLANE;

        #pragma unroll
        for (int k16 = 0; k16 < 4; k16++) {
            uint32_t ah[4][4], al[4][4];
            uint32_t bh[4][2], bl[4][2];
            #pragma unroll
            for (int mi = 0; mi < 4; mi++) {
                int row = wm + mi * 16 + arow_l;
                uint32_t c = (uint32_t)((k16 * 2 + seg) ^ (row & 7));
                uint32_t addr = aBase + (uint32_t)(row * 128) + c * 16;
                ldm_x4(ah[mi], addr);
                ldm_x4(al[mi], addr + A_PLANE);
            }
            #pragma unroll
            for (int ng = 0; ng < 2; ng++) {
                int row = wn + ng * 16 + arow_l;
                uint32_t c = (uint32_t)((k16 * 2 + seg) ^ (row & 7));
                uint32_t addr = bBase + (uint32_t)(row * 128) + c * 16;
                uint32_t t[4];
                ldm_x4(t, addr);
                bh[2 * ng][0] = t[0]; bh[2 * ng][1] = t[2];
                bh[2 * ng + 1][0] = t[1]; bh[2 * ng + 1][1] = t[3];
                ldm_x4(t, addr + B_PLANE);
                bl[2 * ng][0] = t[0]; bl[2 * ng][1] = t[2];
                bl[2 * ng + 1][0] = t[1]; bl[2 * ng + 1][1] = t[3];
            }
            #pragma unroll
            for (int mi = 0; mi < 4; mi++)
                #pragma unroll
                for (int ni = 0; ni < 4; ni++) {
                    mma_bf16(acc[mi][ni], ah[mi], bh[ni][0], bh[ni][1]);
                    mma_bf16(acc[mi][ni], ah[mi], bl[ni][0], bl[ni][1]);
                    mma_bf16(acc[mi][ni], al[mi], bh[ni][0], bh[ni][1]);
                }
        }
        __syncthreads();   // all warps done reading buffer s before refill

        if (i + NSTAGE < nch)
            stage_chunk(sb + s * STAGE_BYTES, Ahi, Alo, Bhi, Blo,
                        bm, bn, (i + NSTAGE) * BK, K, tid);
    }

    // epilogue: bias + relu + bf16 hi/lo split, packed u32 stores
    int qr = lane >> 2;            // 0..7
    int qc = (lane & 3) * 2;       // 0,2,4,6
    #pragma unroll
    for (int mi = 0; mi < 4; mi++) {
        #pragma unroll
        for (int ni = 0; ni < 4; ni++) {
            int col = bn + wn + ni * 8 + qc;
            float b0 = bias[col], b1 = bias[col + 1];
            #pragma unroll
            for (int half = 0; half < 2; half++) {
                int row = bm + wm + mi * 16 + qr + half * 8;
                float v0 = acc[mi][ni][half * 2 + 0] + b0;
                float v1 = acc[mi][ni][half * 2 + 1] + b1;
                v0 = fmaxf(v0, 0.f); v1 = fmaxf(v1, 0.f);
                __nv_bfloat16 h0 = __float2bfloat16(v0);
                __nv_bfloat16 h1 = __float2bfloat16(v1);
                __nv_bfloat16 l0 = __float2bfloat16(v0 - __bfloat162float(h0));
                __nv_bfloat16 l1 = __float2bfloat16(v1 - __bfloat162float(h1));
                size_t go = (size_t)row * (H_DIM / 2) + (col >> 1);
                Chi32[go] = ((uint32_t)__bfloat16_as_ushort(h1) << 16) | __bfloat16_as_ushort(h0);
                Clo32[go] = ((uint32_t)__bfloat16_as_ushort(l1) << 16) | __bfloat16_as_ushort(l0);
            }
        }
    }
}

// ---------------- RVQ: indices, loss, z_sum ----------------
__global__ void vq_kernel(const float* __restrict__ latents,
                          const int*   __restrict__ latent_idx,
                          const float* __restrict__ codebooks,
                          float* __restrict__ out_tail, int write_tail)
{
    __shared__ float s_img[S_STAGES][D_DIM];
    __shared__ float s_min[256];
    __shared__ int   s_mi[256];
    __shared__ int   s_idx[S_STAGES];

    int tid = threadIdx.x;
    int li = latent_idx[0];
    const float* img = latents + (size_t)li * S_STAGES * D_DIM;
    if (tid < S_STAGES * D_DIM) s_img[tid / D_DIM][tid % D_DIM] = img[tid];
    __syncthreads();

    for (int s = 0; s < S_STAGES; s++) {
        const float* z = s_img[s];
        float zz = 0.f;
        #pragma unroll
        for (int d = 0; d < D_DIM; d++) zz = fmaf(z[d], z[d], zz);
        float bmin = INFINITY; int bidx = 0x7fffffff;
        for (int k = tid; k < K_CODES; k += 256) {
            const float* e = codebooks + ((size_t)s * K_CODES + k) * D_DIM;
            float dot = 0.f, ee = 0.f;
            #pragma unroll
            for (int d = 0; d < D_DIM; d++) {
                float ev = e[d];
                dot = fmaf(z[d], ev, dot);
                ee  = fmaf(ev, ev, ee);
            }
            float dist = zz - 2.f * dot + ee;
            if (dist < bmin || (dist == bmin && k < bidx)) { bmin = dist; bidx = k; }
        }
        s_min[tid] = bmin; s_mi[tid] = bidx;
        __syncthreads();
        for (int off = 128; off > 0; off >>= 1) {
            if (tid < off) {
                float om = s_min[tid + off]; int oi = s_mi[tid + off];
                if (om < s_min[tid] || (om == s_min[tid] && oi < s_mi[tid])) {
                    s_min[tid] = om; s_mi[tid] = oi;
                }
            }
            __syncthreads();
        }
        if (tid == 0) s_idx[s] = s_mi[0];
        __syncthreads();
    }

    if (tid < D_DIM) {
        float v = 0.f;
        #pragma unroll
        for (int s = 0; s < S_STAGES; s++) v += s_img[s][tid];
        g_zsum[tid] = v;
    }
    if (tid == 0 && write_tail) {
        float loss = 0.f;
        for (int s = 0; s < S_STAGES; s++) {
            const float* e = codebooks + ((size_t)s * K_CODES + s_idx[s]) * D_DIM;
            float acc = 0.f;
            for (int d = 0; d < D_DIM; d++) {
                float df = e[d] - s_img[s][d];
                acc = fmaf(df, df, acc);
            }
            loss += 0.25f * (acc / (float)D_DIM);
        }
        for (int s = 0; s < S_STAGES; s++) out_tail[s] = (float)s_idx[s];
        out_tail[S_STAGES] = loss;
    }
}

// ---------------- combined bias: mod_b + zsum@mod_W + dec bias ----------------
__global__ void bias_kernel(const float* __restrict__ mod_W, const float* __restrict__ mod_b,
                            const float* __restrict__ dec_b0, const float* __restrict__ dec_bh)
{
    __shared__ float zs[D_DIM];
    int j = blockIdx.x * 256 + threadIdx.x;   // < 5120
    if (threadIdx.x < D_DIM) zs[threadIdx.x] = g_zsum[threadIdx.x];
    __syncthreads();
    int l = j >> 10, h = j & 1023;
    float acc = mod_b[j];
    #pragma unroll 8
    for (int d = 0; d < D_DIM; d++)
        acc = fmaf(zs[d], mod_W[((size_t)l * D_DIM + d) * H_DIM + h], acc);
    acc += (l == 0) ? dec_b0[h] : dec_bh[(size_t)(l - 1) * H_DIM + h];
    g_bias[j] = acc;
}

// ---------------- positional encoding -> bf16 hi/lo planes (K padded to 128) ----------------
__global__ void pe_kernel(const float* __restrict__ coords)
{
    int idx = blockIdx.x * blockDim.x + threadIdx.x;
    if (idx >= B_PTS * K0_PAD) return;
    int b = idx >> 7, j = idx & 127;
    float v = 0.f;
    if (j < C_DIM) {
        v = coords[b * C_DIM + j];
    } else if (j < IN_DIM) {
        int r = j - C_DIM;
        int f = r >> 2;
        int t = (r >> 1) & 1;
        int c = r & 1;
        float fp = ldexpf(3.14159265358979323846f, f);
        float ang = coords[b * C_DIM + c] * fp;
        v = t ? cosf(ang) : sinf(ang);
    }
    __nv_bfloat16 h = __float2bfloat16(v);
    ((__nv_bfloat16*)g_pe_hi)[idx] = h;
    ((__nv_bfloat16*)g_pe_lo)[idx] = __float2bfloat16(v - __bfloat162float(h));
}

// ---------------- weight transpose + bf16 hi/lo split ----------------
// src [z][Ksrc][N] fp32 -> dst [z][N][Kpad] bf16 (zero-padded K)
__global__ void wtrans_kernel(const float* __restrict__ src, int Ksrc, int Kpad, int Ncols,
                              uint32_t* __restrict__ dst_hi32, uint32_t* __restrict__ dst_lo32)
{
    int z = blockIdx.z;
    const float* s = src + (size_t)z * Ksrc * Ncols;
    __nv_bfloat16* dh = (__nv_bfloat16*)dst_hi32 + (size_t)z * Ncols * Kpad;
    __nv_bfloat16* dl = (__nv_bfloat16*)dst_lo32 + (size_t)z * Ncols * Kpad;
    __shared__ float tile[32][33];
    int k0 = blockIdx.x * 32, n0 = blockIdx.y * 32;
    for (int yy = threadIdx.y; yy < 32; yy += 8) {
        int k = k0 + yy;
        tile[yy][threadIdx.x] = (k < Ksrc) ? s[(size_t)k * Ncols + n0 + threadIdx.x] : 0.f;
    }
    __syncthreads();
    for (int yy = threadIdx.y; yy < 32; yy += 8) {
        int n = n0 + yy, k = k0 + threadIdx.x;
        float v = tile[threadIdx.x][yy];
        __nv_bfloat16 h = __float2bfloat16(v);
        dh[(size_t)n * Kpad + k] = h;
        dl[(size_t)n * Kpad + k] = __float2bfloat16(v - __bfloat162float(h));
    }
}

// ---------------- output projection (H -> 3) ----------------
__global__ void out_kernel(const uint32_t* __restrict__ hi32, const uint32_t* __restrict__ lo32,
                           const float* __restrict__ Wout, const float* __restrict__ bout,
                           float* __restrict__ out)
{
    int b = blockIdx.x;
    int tid = threadIdx.x;
    const uint32_t* h32 = hi32 + (size_t)b * (H_DIM / 2);
    const uint32_t* l32 = lo32 + (size_t)b * (H_DIM / 2);
    float a0 = 0.f, a1 = 0.f, a2 = 0.f;
    for (int k2 = tid; k2 < H_DIM / 2; k2 += 128) {
        uint32_t hv = h32[k2], lv = l32[k2];
        __nv_bfloat162 hp = *reinterpret_cast<const __nv_bfloat162*>(&hv);
        __nv_bfloat162 lp = *reinterpret_cast<const __nv_bfloat162*>(&lv);
        float2 hf = __bfloat1622float2(hp);
        float2 lf = __bfloat1622float2(lp);
        float v0 = hf.x + lf.x, v1 = hf.y + lf.y;
        int k = 2 * k2;
        a0 = fmaf(v0, Wout[k * 3 + 0], a0); a0 = fmaf(v1, Wout[(k + 1) * 3 + 0], a0);
        a1 = fmaf(v0, Wout[k * 3 + 1], a1); a1 = fmaf(v1, Wout[(k + 1) * 3 + 1], a1);
        a2 = fmaf(v0, Wout[k * 3 + 2], a2); a2 = fmaf(v1, Wout[(k + 1) * 3 + 2], a2);
    }
    #pragma unroll
    for (int off = 16; off; off >>= 1) {
        a0 += __shfl_down_sync(0xffffffffu, a0, off);
        a1 += __shfl_down_sync(0xffffffffu, a1, off);
        a2 += __shfl_down_sync(0xffffffffu, a2, off);
    }
    __shared__ float sr[4][3];
    int w = tid >> 5;
    if ((tid & 31) == 0) { sr[w][0] = a0; sr[w][1] = a1; sr[w][2] = a2; }
    __syncthreads();
    if (tid < V_OUT) {
        float v = bout[tid];
        #pragma unroll
        for (int ww = 0; ww < 4; ww++) v += sr[ww][tid];
        out[(size_t)b * V_OUT + tid] = v;
    }
}

// ---------------- launch ----------------
extern "C" void kernel_launch(void* const* d_in, const int* in_sizes, int n_in,
                              void* d_out, int out_size)
{
    const float* coords    = (const float*)d_in[0];
    const int*   latent_ix = (const int*)  d_in[1];
    const float* latents   = (const float*)d_in[2];
    const float* codebooks = (const float*)d_in[3];
    const float* mod_W     = (const float*)d_in[4];
    const float* mod_b     = (const float*)d_in[5];
    const float* dec_W0    = (const float*)d_in[6];
    const float* dec_b0    = (const float*)d_in[7];
    const float* dec_Wh    = (const float*)d_in[8];
    const float* dec_bh    = (const float*)d_in[9];
    const float* dec_Wout  = (const float*)d_in[10];
    const float* dec_bout  = (const float*)d_in[11];
    float* out = (float*)d_out;

    const int values_n = B_PTS * V_OUT;
    int write_tail = (out_size >= values_n + S_STAGES + 1) ? 1 : 0;

    cudaFuncSetAttribute(mlp_layer_kernel, cudaFuncAttributeMaxDynamicSharedMemorySize, SMEM_TOTAL);

    uint32_t *Ahi, *Alo, *Bhi, *Blo, *peh, *pel, *w0h, *w0l, *whh, *whl;
    float *bias;
    cudaGetSymbolAddress((void**)&Ahi, g_actA_hi);
    cudaGetSymbolAddress((void**)&Alo, g_actA_lo);
    cudaGetSymbolAddress((void**)&Bhi, g_actB_hi);
    cudaGetSymbolAddress((void**)&Blo, g_actB_lo);
    cudaGetSymbolAddress((void**)&peh, g_pe_hi);
    cudaGetSymbolAddress((void**)&pel, g_pe_lo);
    cudaGetSymbolAddress((void**)&w0h, g_w0t_hi);
    cudaGetSymbolAddress((void**)&w0l, g_w0t_lo);
    cudaGetSymbolAddress((void**)&whh, g_wht_hi);
    cudaGetSymbolAddress((void**)&whl, g_wht_lo);
    cudaGetSymbolAddress((void**)&bias, g_bias);

    // prep
    vq_kernel<<<1, 256>>>(latents, latent_ix, codebooks, out + values_n, write_tail);
    bias_kernel<<<20, 256>>>(mod_W, mod_b, dec_b0, dec_bh);
    pe_kernel<<<(B_PTS * K0_PAD + 255) / 256, 256>>>(coords);
    {
        dim3 blk(32, 8);
        wtrans_kernel<<<dim3(K0_PAD / 32, H_DIM / 32, 1), blk>>>(dec_W0, IN_DIM, K0_PAD, H_DIM, w0h, w0l);
        wtrans_kernel<<<dim3(H_DIM / 32, H_DIM / 32, 4), blk>>>(dec_Wh, H_DIM, H_DIM, H_DIM, whh, whl);
    }

    dim3 grid(H_DIM / BN, B_PTS / BM);   // (8, 256) = 2048 CTAs
    size_t WH = (size_t)H_DIM * H_DIM / 2;

    // layer 0: pe(128) @ W0^T -> actA
    mlp_layer_kernel<<<grid, THREADS, SMEM_TOTAL>>>(peh, pel, w0h, w0l, bias + 0 * H_DIM, Ahi, Alo, K0_PAD);
    // hidden layers 1..4 (ping-pong actA <-> actB)
    mlp_layer_kernel<<<grid, THREADS, SMEM_TOTAL>>>(Ahi, Alo, whh + 0 * WH, whl + 0 * WH, bias + 1 * H_DIM, Bhi, Blo, H_DIM);
    mlp_layer_kernel<<<grid, THREADS, SMEM_TOTAL>>>(Bhi, Blo, whh + 1 * WH, whl + 1 * WH, bias + 2 * H_DIM, Ahi, Alo, H_DIM);
    mlp_layer_kernel<<<grid, THREADS, SMEM_TOTAL>>>(Ahi, Alo, whh + 2 * WH, whl + 2 * WH, bias + 3 * H_DIM, Bhi, Blo, H_DIM);
    mlp_layer_kernel<<<grid, THREADS, SMEM_TOTAL>>>(Bhi, Blo, whh + 3 * WH, whl + 3 * WH, bias + 4 * H_DIM, Ahi, Alo, H_DIM);
    // output projection
    out_kernel<<<B_PTS, 128>>>(Ahi, Alo, dec_Wout, dec_bout, out);
}

// round 14
// speedup vs baseline: 3.4354x; 1.5896x over previous
#include <cuda_runtime.h>
#include <cuda_fp16.h>
#include <stdint.h>
#include <math.h>

// ---------------- problem constants ----------------
#define B_PTS    65536
#define C_DIM    2
#define V_OUT    3
#define D_DIM    64
#define K_CODES  1024
#define S_STAGES 4
#define H_DIM    1024
#define L_LAYERS 5
#define F_FREQ   25
#define IN_DIM   102       // C*(2F+1)
#define K0_PAD   128       // layer-0 K padded to 2 chunks of 64

// ---------------- GEMM tiling ----------------
#define BM 256
#define BN 128
#define BK 64
#define NSTAGE 3
#define THREADS 512
#define A_PLANE  32768                          // 256 rows x 128B (64 fp16)
#define B_PLANE  16384                          // 128 rows x 128B
#define STAGE_BYTES  (A_PLANE + 2*B_PLANE)      // 64KB (A single plane, W hi+lo)
#define SMEM_TOTAL   (NSTAGE*STAGE_BYTES)       // 192KB

// ---------------- device scratch (static, allocation-free; u32-backed fp16 planes) ----------------
__device__ __align__(256) uint32_t g_actA[(size_t)B_PTS * H_DIM / 2];   // fp16 activations ping
__device__ __align__(256) uint32_t g_actB[(size_t)B_PTS * H_DIM / 2];   // fp16 activations pong
__device__ __align__(256) uint32_t g_pe[(size_t)B_PTS * K0_PAD / 2];    // fp16 positional encoding
__device__ __align__(256) uint32_t g_w0t_h[H_DIM * K0_PAD / 2];
__device__ __align__(256) uint32_t g_w0t_l[H_DIM * K0_PAD / 2];
__device__ __align__(256) uint32_t g_wht_h[4ull * H_DIM * H_DIM / 2];
__device__ __align__(256) uint32_t g_wht_l[4ull * H_DIM * H_DIM / 2];
__device__ float g_bias[L_LAYERS * H_DIM];
__device__ float g_zsum[D_DIM];

// ---------------- PTX helpers (baseline sm_80+, valid on base sm_103) ----------------
__device__ __forceinline__ uint32_t smem_u32(const void* p) {
    uint32_t a;
    asm("{ .reg .u64 t; cvta.to.shared.u64 t, %1; cvt.u32.u64 %0, t; }" : "=r"(a) : "l"(p));
    return a;
}
__device__ __forceinline__ void cp_async16(uint32_t dst, const void* src) {
    asm volatile("cp.async.cg.shared.global [%0], [%1], 16;" :: "r"(dst), "l"(src) : "memory");
}
__device__ __forceinline__ void ldm_x4(uint32_t* r, uint32_t addr) {
    asm volatile("ldmatrix.sync.aligned.m8n8.x4.shared.b16 {%0,%1,%2,%3}, [%4];"
        : "=r"(r[0]), "=r"(r[1]), "=r"(r[2]), "=r"(r[3]) : "r"(addr));
}
__device__ __forceinline__ void mma_f16(float* c, const uint32_t* a, uint32_t b0, uint32_t b1) {
    asm volatile("mma.sync.aligned.m16n8k16.row.col.f32.f16.f16.f32 "
        "{%0,%1,%2,%3}, {%4,%5,%6,%7}, {%8,%9}, {%0,%1,%2,%3};"
        : "+f"(c[0]), "+f"(c[1]), "+f"(c[2]), "+f"(c[3])
        : "r"(a[0]), "r"(a[1]), "r"(a[2]), "r"(a[3]), "r"(b0), "r"(b1));
}

// ---------------- staging: one K-chunk of A + W(hi,lo) via cp.async ----------------
// planes are [rows][128B] with XOR swizzle: 16B chunk c of row stored at c ^ (row & 7).
__device__ __forceinline__ void stage_chunk(
    uint32_t stage_base,
    const __half* A, const __half* Wh, const __half* Wl,
    int bm, int bn, int kc, int K, int tid)
{
    // A plane: 256 rows x 8 granules = 2048 granules of 16B
    #pragma unroll
    for (int it = 0; it < 4; it++) {
        int g = tid + it * THREADS;
        int row = g >> 3, c = g & 7;
        uint32_t d = stage_base + (uint32_t)(row * 128 + ((c ^ (row & 7)) * 16));
        cp_async16(d, A + (size_t)(bm + row) * K + kc + c * 8);
    }
    // W planes: 128 rows x 8 granules = 1024 granules each
    #pragma unroll
    for (int it = 0; it < 2; it++) {
        int g = tid + it * THREADS;
        int row = g >> 3, c = g & 7;
        uint32_t d = stage_base + A_PLANE + (uint32_t)(row * 128 + ((c ^ (row & 7)) * 16));
        size_t boff = (size_t)(bn + row) * K + kc + c * 8;
        cp_async16(d,           Wh + boff);
        cp_async16(d + B_PLANE, Wl + boff);
    }
    asm volatile("cp.async.commit_group;" ::: "memory");
}

// ---------------- tensor-core MLP layer (mma.sync fp16, 2-term weight split) ----------------
// C[M,N] = relu(A @ W^T + bias); A fp16 [M,K] row-major; W = Wh+Wl fp16 [N,K] K-major.
__global__ void __launch_bounds__(THREADS, 1)
mlp_layer_kernel(const uint32_t* __restrict__ A32,
                 const uint32_t* __restrict__ Wh32, const uint32_t* __restrict__ Wl32,
                 const float* __restrict__ bias,
                 uint32_t* __restrict__ C32,
                 int K)
{
    extern __shared__ char smem[];
    uint32_t sb = smem_u32(smem);
    int tid  = threadIdx.x;
    int lane = tid & 31;
    int wid  = tid >> 5;                   // 0..15
    int wm = (wid >> 2) * 64;              // warp M offset (0,64,128,192)
    int wn = (wid & 3) * 32;               // warp N offset (0,32,64,96)
    int bm = blockIdx.y * BM;
    int bn = blockIdx.x * BN;
    int nch = K / BK;

    const __half* A  = (const __half*)A32;
    const __half* Wh = (const __half*)Wh32;
    const __half* Wl = (const __half*)Wl32;

    float acc[4][4][4];
    #pragma unroll
    for (int mi = 0; mi < 4; mi++)
        #pragma unroll
        for (int ni = 0; ni < 4; ni++)
            #pragma unroll
            for (int r = 0; r < 4; r++) acc[mi][ni][r] = 0.f;

    // prologue: fill pipeline
    int npro = (nch < NSTAGE) ? nch : NSTAGE;
    for (int p = 0; p < npro; p++)
        stage_chunk(sb + p * STAGE_BYTES, A, Wh, Wl, bm, bn, p * BK, K, tid);

    int arow_l = lane & 15;       // row within 16-row tile
    int seg    = lane >> 4;       // k-segment half (0/1)

    for (int i = 0; i < nch; i++) {
        int s = i % NSTAGE;
        int rem = nch - 1 - i;
        if (rem >= 2)      asm volatile("cp.async.wait_group 2;" ::: "memory");
        else if (rem == 1) asm volatile("cp.async.wait_group 1;" ::: "memory");
        else               asm volatile("cp.async.wait_group 0;" ::: "memory");
        __syncthreads();

        uint32_t aBase = sb + s * STAGE_BYTES;
        uint32_t bBase = aBase + A_PLANE;

        #pragma unroll
        for (int k16 = 0; k16 < 4; k16++) {
            uint32_t af[4][4];
            uint32_t bh[4][2], bl[4][2];
            #pragma unroll
            for (int mi = 0; mi < 4; mi++) {
                int row = wm + mi * 16 + arow_l;
                uint32_t c = (uint32_t)((k16 * 2 + seg) ^ (row & 7));
                ldm_x4(af[mi], aBase + (uint32_t)(row * 128) + c * 16);
            }
            #pragma unroll
            for (int ng = 0; ng < 2; ng++) {
                int row = wn + ng * 16 + arow_l;
                uint32_t c = (uint32_t)((k16 * 2 + seg) ^ (row & 7));
                uint32_t addr = bBase + (uint32_t)(row * 128) + c * 16;
                uint32_t t[4];
                ldm_x4(t, addr);
                bh[2 * ng][0] = t[0]; bh[2 * ng][1] = t[2];
                bh[2 * ng + 1][0] = t[1]; bh[2 * ng + 1][1] = t[3];
                ldm_x4(t, addr + B_PLANE);
                bl[2 * ng][0] = t[0]; bl[2 * ng][1] = t[2];
                bl[2 * ng + 1][0] = t[1]; bl[2 * ng + 1][1] = t[3];
            }
            #pragma unroll
            for (int mi = 0; mi < 4; mi++)
                #pragma unroll
                for (int ni = 0; ni < 4; ni++) {
                    mma_f16(acc[mi][ni], af[mi], bh[ni][0], bh[ni][1]);
                    mma_f16(acc[mi][ni], af[mi], bl[ni][0], bl[ni][1]);
                }
        }
        __syncthreads();   // all warps done reading buffer s before refill

        if (i + NSTAGE < nch)
            stage_chunk(sb + s * STAGE_BYTES, A, Wh, Wl, bm, bn, (i + NSTAGE) * BK, K, tid);
    }

    // epilogue: bias + relu -> fp16, packed u32 stores
    int qr = lane >> 2;            // 0..7
    int qc = (lane & 3) * 2;       // 0,2,4,6
    #pragma unroll
    for (int mi = 0; mi < 4; mi++) {
        #pragma unroll
        for (int ni = 0; ni < 4; ni++) {
            int col = bn + wn + ni * 8 + qc;
            float b0 = bias[col], b1 = bias[col + 1];
            #pragma unroll
            for (int half = 0; half < 2; half++) {
                int row = bm + wm + mi * 16 + qr + half * 8;
                float v0 = fmaxf(acc[mi][ni][half * 2 + 0] + b0, 0.f);
                float v1 = fmaxf(acc[mi][ni][half * 2 + 1] + b1, 0.f);
                __half2 p = __floats2half2_rn(v0, v1);
                C32[(size_t)row * (H_DIM / 2) + (col >> 1)] = *reinterpret_cast<uint32_t*>(&p);
            }
        }
    }
}

// ---------------- RVQ: indices, loss, z_sum ----------------
__global__ void vq_kernel(const float* __restrict__ latents,
                          const int*   __restrict__ latent_idx,
                          const float* __restrict__ codebooks,
                          float* __restrict__ out_tail, int write_tail)
{
    __shared__ float s_img[S_STAGES][D_DIM];
    __shared__ float s_min[256];
    __shared__ int   s_mi[256];
    __shared__ int   s_idx[S_STAGES];

    int tid = threadIdx.x;
    int li = latent_idx[0];
    const float* img = latents + (size_t)li * S_STAGES * D_DIM;
    if (tid < S_STAGES * D_DIM) s_img[tid / D_DIM][tid % D_DIM] = img[tid];
    __syncthreads();

    for (int s = 0; s < S_STAGES; s++) {
        const float* z = s_img[s];
        float zz = 0.f;
        #pragma unroll
        for (int d = 0; d < D_DIM; d++) zz = fmaf(z[d], z[d], zz);
        float bmin = INFINITY; int bidx = 0x7fffffff;
        for (int k = tid; k < K_CODES; k += 256) {
            const float* e = codebooks + ((size_t)s * K_CODES + k) * D_DIM;
            float dot = 0.f, ee = 0.f;
            #pragma unroll
            for (int d = 0; d < D_DIM; d++) {
                float ev = e[d];
                dot = fmaf(z[d], ev, dot);
                ee  = fmaf(ev, ev, ee);
            }
            float dist = zz - 2.f * dot + ee;
            if (dist < bmin || (dist == bmin && k < bidx)) { bmin = dist; bidx = k; }
        }
        s_min[tid] = bmin; s_mi[tid] = bidx;
        __syncthreads();
        for (int off = 128; off > 0; off >>= 1) {
            if (tid < off) {
                float om = s_min[tid + off]; int oi = s_mi[tid + off];
                if (om < s_min[tid] || (om == s_min[tid] && oi < s_mi[tid])) {
                    s_min[tid] = om; s_mi[tid] = oi;
                }
            }
            __syncthreads();
        }
        if (tid == 0) s_idx[s] = s_mi[0];
        __syncthreads();
    }

    if (tid < D_DIM) {
        float v = 0.f;
        #pragma unroll
        for (int s = 0; s < S_STAGES; s++) v += s_img[s][tid];
        g_zsum[tid] = v;
    }
    if (tid == 0 && write_tail) {
        float loss = 0.f;
        for (int s = 0; s < S_STAGES; s++) {
            const float* e = codebooks + ((size_t)s * K_CODES + s_idx[s]) * D_DIM;
            float acc = 0.f;
            for (int d = 0; d < D_DIM; d++) {
                float df = e[d] - s_img[s][d];
                acc = fmaf(df, df, acc);
            }
            loss += 0.25f * (acc / (float)D_DIM);
        }
        for (int s = 0; s < S_STAGES; s++) out_tail[s] = (float)s_idx[s];
        out_tail[S_STAGES] = loss;
    }
}

// ---------------- combined bias: mod_b + zsum@mod_W + dec bias ----------------
__global__ void bias_kernel(const float* __restrict__ mod_W, const float* __restrict__ mod_b,
                            const float* __restrict__ dec_b0, const float* __restrict__ dec_bh)
{
    __shared__ float zs[D_DIM];
    int j = blockIdx.x * 256 + threadIdx.x;   // < 5120
    if (threadIdx.x < D_DIM) zs[threadIdx.x] = g_zsum[threadIdx.x];
    __syncthreads();
    int l = j >> 10, h = j & 1023;
    float acc = mod_b[j];
    #pragma unroll 8
    for (int d = 0; d < D_DIM; d++)
        acc = fmaf(zs[d], mod_W[((size_t)l * D_DIM + d) * H_DIM + h], acc);
    acc += (l == 0) ? dec_b0[h] : dec_bh[(size_t)(l - 1) * H_DIM + h];
    g_bias[j] = acc;
}

// ---------------- positional encoding -> fp16 plane (K padded to 128) ----------------
__global__ void pe_kernel(const float* __restrict__ coords)
{
    int idx = blockIdx.x * blockDim.x + threadIdx.x;
    if (idx >= B_PTS * K0_PAD) return;
    int b = idx >> 7, j = idx & 127;
    float v = 0.f;
    if (j < C_DIM) {
        v = coords[b * C_DIM + j];
    } else if (j < IN_DIM) {
        int r = j - C_DIM;
        int f = r >> 2;
        int t = (r >> 1) & 1;
        int c = r & 1;
        float fp = ldexpf(3.14159265358979323846f, f);
        float ang = coords[b * C_DIM + c] * fp;
        v = t ? cosf(ang) : sinf(ang);
    }
    ((__half*)g_pe)[idx] = __float2half_rn(v);
}

// ---------------- weight transpose + fp16 hi/lo split ----------------
// src [z][Ksrc][N] fp32 -> dst [z][N][Kpad] fp16 (zero-padded K)
__global__ void wtrans_kernel(const float* __restrict__ src, int Ksrc, int Kpad, int Ncols,
                              uint32_t* __restrict__ dst_h32, uint32_t* __restrict__ dst_l32)
{
    int z = blockIdx.z;
    const float* s = src + (size_t)z * Ksrc * Ncols;
    __half* dh = (__half*)dst_h32 + (size_t)z * Ncols * Kpad;
    __half* dl = (__half*)dst_l32 + (size_t)z * Ncols * Kpad;
    __shared__ float tile[32][33];
    int k0 = blockIdx.x * 32, n0 = blockIdx.y * 32;
    for (int yy = threadIdx.y; yy < 32; yy += 8) {
        int k = k0 + yy;
        tile[yy][threadIdx.x] = (k < Ksrc) ? s[(size_t)k * Ncols + n0 + threadIdx.x] : 0.f;
    }
    __syncthreads();
    for (int yy = threadIdx.y; yy < 32; yy += 8) {
        int n = n0 + yy, k = k0 + threadIdx.x;
        float v = tile[threadIdx.x][yy];
        __half h = __float2half_rn(v);
        dh[(size_t)n * Kpad + k] = h;
        dl[(size_t)n * Kpad + k] = __float2half_rn(v - __half2float(h));
    }
}

// ---------------- output projection (H -> 3) ----------------
__global__ void out_kernel(const uint32_t* __restrict__ h32in,
                           const float* __restrict__ Wout, const float* __restrict__ bout,
                           float* __restrict__ out)
{
    int b = blockIdx.x;
    int tid = threadIdx.x;
    const uint32_t* h32 = h32in + (size_t)b * (H_DIM / 2);
    float a0 = 0.f, a1 = 0.f, a2 = 0.f;
    for (int k2 = tid; k2 < H_DIM / 2; k2 += 128) {
        uint32_t hv = h32[k2];
        __half2 hp = *reinterpret_cast<const __half2*>(&hv);
        float2 hf = __half22float2(hp);
        int k = 2 * k2;
        a0 = fmaf(hf.x, Wout[k * 3 + 0], a0); a0 = fmaf(hf.y, Wout[(k + 1) * 3 + 0], a0);
        a1 = fmaf(hf.x, Wout[k * 3 + 1], a1); a1 = fmaf(hf.y, Wout[(k + 1) * 3 + 1], a1);
        a2 = fmaf(hf.x, Wout[k * 3 + 2], a2); a2 = fmaf(hf.y, Wout[(k + 1) * 3 + 2], a2);
    }
    #pragma unroll
    for (int off = 16; off; off >>= 1) {
        a0 += __shfl_down_sync(0xffffffffu, a0, off);
        a1 += __shfl_down_sync(0xffffffffu, a1, off);
        a2 += __shfl_down_sync(0xffffffffu, a2, off);
    }
    __shared__ float sr[4][3];
    int w = tid >> 5;
    if ((tid & 31) == 0) { sr[w][0] = a0; sr[w][1] = a1; sr[w][2] = a2; }
    __syncthreads();
    if (tid < V_OUT) {
        float v = bout[tid];
        #pragma unroll
        for (int ww = 0; ww < 4; ww++) v += sr[ww][tid];
        out[(size_t)b * V_OUT + tid] = v;
    }
}

// ---------------- launch ----------------
extern "C" void kernel_launch(void* const* d_in, const int* in_sizes, int n_in,
                              void* d_out, int out_size)
{
    const float* coords    = (const float*)d_in[0];
    const int*   latent_ix = (const int*)  d_in[1];
    const float* latents   = (const float*)d_in[2];
    const float* codebooks = (const float*)d_in[3];
    const float* mod_W     = (const float*)d_in[4];
    const float* mod_b     = (const float*)d_in[5];
    const float* dec_W0    = (const float*)d_in[6];
    const float* dec_b0    = (const float*)d_in[7];
    const float* dec_Wh    = (const float*)d_in[8];
    const float* dec_bh    = (const float*)d_in[9];
    const float* dec_Wout  = (const float*)d_in[10];
    const float* dec_bout  = (const float*)d_in[11];
    float* out = (float*)d_out;

    const int values_n = B_PTS * V_OUT;
    int write_tail = (out_size >= values_n + S_STAGES + 1) ? 1 : 0;

    cudaFuncSetAttribute(mlp_layer_kernel, cudaFuncAttributeMaxDynamicSharedMemorySize, SMEM_TOTAL);

    uint32_t *Aact, *Bact, *pe, *w0h, *w0l, *whh, *whl;
    float *bias;
    cudaGetSymbolAddress((void**)&Aact, g_actA);
    cudaGetSymbolAddress((void**)&Bact, g_actB);
    cudaGetSymbolAddress((void**)&pe,   g_pe);
    cudaGetSymbolAddress((void**)&w0h,  g_w0t_h);
    cudaGetSymbolAddress((void**)&w0l,  g_w0t_l);
    cudaGetSymbolAddress((void**)&whh,  g_wht_h);
    cudaGetSymbolAddress((void**)&whl,  g_wht_l);
    cudaGetSymbolAddress((void**)&bias, g_bias);

    // prep
    vq_kernel<<<1, 256>>>(latents, latent_ix, codebooks, out + values_n, write_tail);
    bias_kernel<<<20, 256>>>(mod_W, mod_b, dec_b0, dec_bh);
    pe_kernel<<<(B_PTS * K0_PAD + 255) / 256, 256>>>(coords);
    {
        dim3 blk(32, 8);
        wtrans_kernel<<<dim3(K0_PAD / 32, H_DIM / 32, 1), blk>>>(dec_W0, IN_DIM, K0_PAD, H_DIM, w0h, w0l);
        wtrans_kernel<<<dim3(H_DIM / 32, H_DIM / 32, 4), blk>>>(dec_Wh, H_DIM, H_DIM, H_DIM, whh, whl);
    }

    dim3 grid(H_DIM / BN, B_PTS / BM);   // (8, 256) = 2048 CTAs
    size_t WH = (size_t)H_DIM * H_DIM / 2;

    // layer 0: pe(128) @ W0^T -> actA
    mlp_layer_kernel<<<grid, THREADS, SMEM_TOTAL>>>(pe, w0h, w0l, bias + 0 * H_DIM, Aact, K0_PAD);
    // hidden layers 1..4 (ping-pong actA <-> actB)
    mlp_layer_kernel<<<grid, THREADS, SMEM_TOTAL>>>(Aact, whh + 0 * WH, whl + 0 * WH, bias + 1 * H_DIM, Bact, H_DIM);
    mlp_layer_kernel<<<grid, THREADS, SMEM_TOTAL>>>(Bact, whh + 1 * WH, whl + 1 * WH, bias + 2 * H_DIM, Aact, H_DIM);
    mlp_layer_kernel<<<grid, THREADS, SMEM_TOTAL>>>(Aact, whh + 2 * WH, whl + 2 * WH, bias + 3 * H_DIM, Bact, H_DIM);
    mlp_layer_kernel<<<grid, THREADS, SMEM_TOTAL>>>(Bact, whh + 3 * WH, whl + 3 * WH, bias + 4 * H_DIM, Aact, H_DIM);
    // output projection
    out_kernel<<<B_PTS, 128>>>(Aact, dec_Wout, dec_bout, out);
}